// round 15
// baseline (speedup 1.0000x reference)
#include <cuda_runtime.h>
#include <cuda_fp16.h>

#define N_NODES   50000
#define IN_FEATS  256
#define OUT_FEATS 128
#define MAX_E     800000

// ---- scratch (device globals; no allocs allowed) ----
__device__ __half g_hw[(size_t)N_NODES * OUT_FEATS];  // projected features (fp16)
__device__ int    g_counts[N_NODES];                  // zeroed by scan_write each run
__device__ int    g_row_ptr[N_NODES + 1];
__device__ int    g_cursor[N_NODES];
__device__ int    g_bsum[256];
__device__ int    g_node_ctr;                         // work-stealing counter (reset by scan_write)
__device__ unsigned long long g_perm[MAX_E];          // packed (src, coeff)

// ===========================================================================
// PTX helpers
// ===========================================================================
__device__ __forceinline__ unsigned smem_addr_u32(const void* ptr)
{
    return static_cast<unsigned>(__cvta_generic_to_shared(ptr));
}

__device__ __forceinline__ void ldsm4(unsigned& x0, unsigned& x1,
                                      unsigned& x2, unsigned& x3, unsigned addr)
{
    asm volatile("ldmatrix.sync.aligned.m8n8.x4.shared.b16 {%0,%1,%2,%3}, [%4];"
                 : "=r"(x0), "=r"(x1), "=r"(x2), "=r"(x3)
                 : "r"(addr));
}

__device__ __forceinline__ void ldsm4t(unsigned& x0, unsigned& x1,
                                       unsigned& x2, unsigned& x3, unsigned addr)
{
    asm volatile("ldmatrix.sync.aligned.m8n8.x4.trans.shared.b16 {%0,%1,%2,%3}, [%4];"
                 : "=r"(x0), "=r"(x1), "=r"(x2), "=r"(x3)
                 : "r"(addr));
}

__device__ __forceinline__ void mma_16816(float& c0, float& c1, float& c2, float& c3,
                                          unsigned a0, unsigned a1, unsigned a2, unsigned a3,
                                          unsigned b0, unsigned b1)
{
    asm volatile(
        "mma.sync.aligned.m16n8k16.row.col.f32.f16.f16.f32 "
        "{%0,%1,%2,%3}, {%4,%5,%6,%7}, {%8,%9}, {%0,%1,%2,%3};"
        : "+f"(c0), "+f"(c1), "+f"(c2), "+f"(c3)
        : "r"(a0), "r"(a1), "r"(a2), "r"(a3), "r"(b0), "r"(b1));
}

// ===========================================================================
// Tensor-core GEMM (measured-best 27us version, verbatim):
// 128x128 block tile, BK=32, double-buffered, register-staged loads.
// ===========================================================================
#define GBM 128
#define A_PAD 40    // halves per Ash row (80 B)
#define B_PAD 136   // halves per Bsh row (272 B)

__global__ __launch_bounds__(256) void gemm_kernel(
    const float* __restrict__ hmat, const float* __restrict__ wmat, int M)
{
    __shared__ __align__(16) __half Ash[2][128][A_PAD];
    __shared__ __align__(16) __half Bsh[2][32][B_PAD];

    const int tid    = threadIdx.x;
    const int lane   = tid & 31;
    const int wid    = tid >> 5;
    const int warp_m = wid & 3;
    const int warp_n = wid >> 2;
    const int block_m = blockIdx.x * GBM;

    const int arow0 = tid >> 2;
    const int arow1 = (tid + 256) >> 2;
    const int acol0 = (tid & 3) * 8;
    const int brow0 = tid >> 4;
    const int brow1 = (tid + 256) >> 4;
    const int bcol0 = (tid & 15) * 8;

    float acc[2][8][4];
#pragma unroll
    for (int mt = 0; mt < 2; mt++)
#pragma unroll
        for (int nt = 0; nt < 8; nt++)
#pragma unroll
            for (int q = 0; q < 4; q++) acc[mt][nt][q] = 0.0f;

    const int ldrow = lane & 15;
    const int ldcol = (lane >> 4) * 8;

    float4 stA[2][2];
    float4 stB[2][2];

    // ---------------- prologue ----------------
    {
        const int grow0 = block_m + arow0;
        const int grow1 = block_m + arow1;
        stA[0][0] = stA[0][1] = make_float4(0.f, 0.f, 0.f, 0.f);
        stA[1][0] = stA[1][1] = make_float4(0.f, 0.f, 0.f, 0.f);
        if (grow0 < M) {
            const float* p = hmat + (size_t)grow0 * IN_FEATS + acol0;
            stA[0][0] = reinterpret_cast<const float4*>(p)[0];
            stA[0][1] = reinterpret_cast<const float4*>(p)[1];
        }
        if (grow1 < M) {
            const float* p = hmat + (size_t)grow1 * IN_FEATS + acol0;
            stA[1][0] = reinterpret_cast<const float4*>(p)[0];
            stA[1][1] = reinterpret_cast<const float4*>(p)[1];
        }
        {
            const float* p = wmat + (size_t)brow0 * OUT_FEATS + bcol0;
            stB[0][0] = reinterpret_cast<const float4*>(p)[0];
            stB[0][1] = reinterpret_cast<const float4*>(p)[1];
        }
        {
            const float* p = wmat + (size_t)brow1 * OUT_FEATS + bcol0;
            stB[1][0] = reinterpret_cast<const float4*>(p)[0];
            stB[1][1] = reinterpret_cast<const float4*>(p)[1];
        }
        __half2 pk[4];
        pk[0] = __floats2half2_rn(stA[0][0].x, stA[0][0].y);
        pk[1] = __floats2half2_rn(stA[0][0].z, stA[0][0].w);
        pk[2] = __floats2half2_rn(stA[0][1].x, stA[0][1].y);
        pk[3] = __floats2half2_rn(stA[0][1].z, stA[0][1].w);
        *reinterpret_cast<uint4*>(&Ash[0][arow0][acol0]) = *reinterpret_cast<const uint4*>(pk);
        pk[0] = __floats2half2_rn(stA[1][0].x, stA[1][0].y);
        pk[1] = __floats2half2_rn(stA[1][0].z, stA[1][0].w);
        pk[2] = __floats2half2_rn(stA[1][1].x, stA[1][1].y);
        pk[3] = __floats2half2_rn(stA[1][1].z, stA[1][1].w);
        *reinterpret_cast<uint4*>(&Ash[0][arow1][acol0]) = *reinterpret_cast<const uint4*>(pk);
        pk[0] = __floats2half2_rn(stB[0][0].x, stB[0][0].y);
        pk[1] = __floats2half2_rn(stB[0][0].z, stB[0][0].w);
        pk[2] = __floats2half2_rn(stB[0][1].x, stB[0][1].y);
        pk[3] = __floats2half2_rn(stB[0][1].z, stB[0][1].w);
        *reinterpret_cast<uint4*>(&Bsh[0][brow0][bcol0]) = *reinterpret_cast<const uint4*>(pk);
        pk[0] = __floats2half2_rn(stB[1][0].x, stB[1][0].y);
        pk[1] = __floats2half2_rn(stB[1][0].z, stB[1][0].w);
        pk[2] = __floats2half2_rn(stB[1][1].x, stB[1][1].y);
        pk[3] = __floats2half2_rn(stB[1][1].z, stB[1][1].w);
        *reinterpret_cast<uint4*>(&Bsh[0][brow1][bcol0]) = *reinterpret_cast<const uint4*>(pk);
    }
    __syncthreads();

    // ---------------- main loop ----------------
    int buf = 0;
    for (int k0 = 0; k0 < IN_FEATS; k0 += 32, buf ^= 1) {
        const bool has_next = (k0 + 32 < IN_FEATS);

        if (has_next) {
            const int kn = k0 + 32;
            const int grow0 = block_m + arow0;
            const int grow1 = block_m + arow1;
            stA[0][0] = stA[0][1] = make_float4(0.f, 0.f, 0.f, 0.f);
            stA[1][0] = stA[1][1] = make_float4(0.f, 0.f, 0.f, 0.f);
            if (grow0 < M) {
                const float* p = hmat + (size_t)grow0 * IN_FEATS + kn + acol0;
                stA[0][0] = reinterpret_cast<const float4*>(p)[0];
                stA[0][1] = reinterpret_cast<const float4*>(p)[1];
            }
            if (grow1 < M) {
                const float* p = hmat + (size_t)grow1 * IN_FEATS + kn + acol0;
                stA[1][0] = reinterpret_cast<const float4*>(p)[0];
                stA[1][1] = reinterpret_cast<const float4*>(p)[1];
            }
            {
                const float* p = wmat + (size_t)(kn + brow0) * OUT_FEATS + bcol0;
                stB[0][0] = reinterpret_cast<const float4*>(p)[0];
                stB[0][1] = reinterpret_cast<const float4*>(p)[1];
            }
            {
                const float* p = wmat + (size_t)(kn + brow1) * OUT_FEATS + bcol0;
                stB[1][0] = reinterpret_cast<const float4*>(p)[0];
                stB[1][1] = reinterpret_cast<const float4*>(p)[1];
            }
        }

#pragma unroll
        for (int kk = 0; kk < 32; kk += 16) {
            unsigned afrag[2][4];
#pragma unroll
            for (int mt = 0; mt < 2; mt++) {
                unsigned addr = smem_addr_u32(
                    &Ash[buf][warp_m * 32 + mt * 16 + ldrow][kk + ldcol]);
                ldsm4(afrag[mt][0], afrag[mt][1], afrag[mt][2], afrag[mt][3], addr);
            }
            unsigned bfrag[4][4];
#pragma unroll
            for (int pp = 0; pp < 4; pp++) {
                unsigned addr = smem_addr_u32(
                    &Bsh[buf][kk + ldrow][warp_n * 64 + pp * 16 + ldcol]);
                ldsm4t(bfrag[pp][0], bfrag[pp][1], bfrag[pp][2], bfrag[pp][3], addr);
            }
#pragma unroll
            for (int mt = 0; mt < 2; mt++) {
#pragma unroll
                for (int nt = 0; nt < 8; nt++) {
                    unsigned bu0 = bfrag[nt >> 1][(nt & 1) * 2];
                    unsigned bu1 = bfrag[nt >> 1][(nt & 1) * 2 + 1];
                    mma_16816(acc[mt][nt][0], acc[mt][nt][1],
                              acc[mt][nt][2], acc[mt][nt][3],
                              afrag[mt][0], afrag[mt][1],
                              afrag[mt][2], afrag[mt][3], bu0, bu1);
                }
            }
        }

        if (has_next) {
            const int nb_ = buf ^ 1;
            __half2 pk[4];
            pk[0] = __floats2half2_rn(stA[0][0].x, stA[0][0].y);
            pk[1] = __floats2half2_rn(stA[0][0].z, stA[0][0].w);
            pk[2] = __floats2half2_rn(stA[0][1].x, stA[0][1].y);
            pk[3] = __floats2half2_rn(stA[0][1].z, stA[0][1].w);
            *reinterpret_cast<uint4*>(&Ash[nb_][arow0][acol0]) = *reinterpret_cast<const uint4*>(pk);
            pk[0] = __floats2half2_rn(stA[1][0].x, stA[1][0].y);
            pk[1] = __floats2half2_rn(stA[1][0].z, stA[1][0].w);
            pk[2] = __floats2half2_rn(stA[1][1].x, stA[1][1].y);
            pk[3] = __floats2half2_rn(stA[1][1].z, stA[1][1].w);
            *reinterpret_cast<uint4*>(&Ash[nb_][arow1][acol0]) = *reinterpret_cast<const uint4*>(pk);
            pk[0] = __floats2half2_rn(stB[0][0].x, stB[0][0].y);
            pk[1] = __floats2half2_rn(stB[0][0].z, stB[0][0].w);
            pk[2] = __floats2half2_rn(stB[0][1].x, stB[0][1].y);
            pk[3] = __floats2half2_rn(stB[0][1].z, stB[0][1].w);
            *reinterpret_cast<uint4*>(&Bsh[nb_][brow0][bcol0]) = *reinterpret_cast<const uint4*>(pk);
            pk[0] = __floats2half2_rn(stB[1][0].x, stB[1][0].y);
            pk[1] = __floats2half2_rn(stB[1][0].z, stB[1][0].w);
            pk[2] = __floats2half2_rn(stB[1][1].x, stB[1][1].y);
            pk[3] = __floats2half2_rn(stB[1][1].z, stB[1][1].w);
            *reinterpret_cast<uint4*>(&Bsh[nb_][brow1][bcol0]) = *reinterpret_cast<const uint4*>(pk);
        }
        __syncthreads();
    }

    // ---- epilogue: fp16 store ----
    const int qrow = lane >> 2;
    const int qcol = lane & 3;
#pragma unroll
    for (int mt = 0; mt < 2; mt++) {
#pragma unroll
        for (int nt = 0; nt < 8; nt++) {
            int col  = warp_n * 64 + nt * 8 + qcol * 2;
            int row0 = block_m + warp_m * 32 + mt * 16 + qrow;
            int row1 = row0 + 8;
            if (row0 < M) {
                *reinterpret_cast<__half2*>(&g_hw[(size_t)row0 * OUT_FEATS + col]) =
                    __floats2half2_rn(acc[mt][nt][0], acc[mt][nt][1]);
            }
            if (row1 < M) {
                *reinterpret_cast<__half2*>(&g_hw[(size_t)row1 * OUT_FEATS + col]) =
                    __floats2half2_rn(acc[mt][nt][2], acc[mt][nt][3]);
            }
        }
    }
}

// ===========================================================================
// CSR build
// ===========================================================================
__global__ void hist_kernel(const int* __restrict__ dst, int E)
{
    int base = (blockIdx.x * blockDim.x + threadIdx.x) * 4;
    if (base + 4 <= E) {
        int4 d4 = *reinterpret_cast<const int4*>(dst + base);
        atomicAdd(&g_counts[d4.x], 1);
        atomicAdd(&g_counts[d4.y], 1);
        atomicAdd(&g_counts[d4.z], 1);
        atomicAdd(&g_counts[d4.w], 1);
    } else {
        for (int k = base; k < E; k++) atomicAdd(&g_counts[dst[k]], 1);
    }
}

__global__ __launch_bounds__(256) void scan_sums_kernel(int N)
{
    __shared__ int sh[256];
    int i = blockIdx.x * 256 + threadIdx.x;
    sh[threadIdx.x] = (i < N) ? g_counts[i] : 0;
    __syncthreads();
#pragma unroll
    for (int s = 128; s > 0; s >>= 1) {
        if (threadIdx.x < s) sh[threadIdx.x] += sh[threadIdx.x + s];
        __syncthreads();
    }
    if (threadIdx.x == 0) g_bsum[blockIdx.x] = sh[0];
}

// Merged top-scan + local scan; initializes cursors, SELF-CLEANS counts,
// and resets the gather work-stealing counter for this replay.
__global__ __launch_bounds__(256) void scan_write_kernel(int nb, int N, int E)
{
    __shared__ int top[256];
    __shared__ int sh[256];
    const int t = threadIdx.x;

    int tv = (t < nb) ? g_bsum[t] : 0;
    top[t] = tv;
    __syncthreads();
#pragma unroll
    for (int s = 1; s < 256; s <<= 1) {
        int add = (t >= s) ? top[t - s] : 0;
        __syncthreads();
        top[t] += add;
        __syncthreads();
    }
    const int boff = (blockIdx.x > 0) ? top[blockIdx.x - 1] : 0;

    int i = blockIdx.x * 256 + t;
    int v = (i < N) ? g_counts[i] : 0;
    sh[t] = v;
    __syncthreads();
#pragma unroll
    for (int s = 1; s < 256; s <<= 1) {
        int add = (t >= s) ? sh[t - s] : 0;
        __syncthreads();
        sh[t] += add;
        __syncthreads();
    }
    if (i < N) {
        int rp = boff + sh[t] - v;
        g_row_ptr[i] = rp;
        g_cursor[i]  = rp;
        g_counts[i]  = 0;          // self-clean for next run
    }
    if (blockIdx.x == 0 && t == 0) {
        g_row_ptr[N] = E;
        g_node_ctr   = 0;          // reset work-stealing counter
    }
}

__device__ __forceinline__ unsigned long long pack_edge(int s, float c)
{
    return (unsigned long long)(unsigned)s |
           ((unsigned long long)__float_as_uint(c) << 32);
}

// Permutation, ILP-4 (best-measured configuration).
__global__ void permute_kernel(
    const int* __restrict__ src, const int* __restrict__ dst,
    const float* __restrict__ norm, const float* __restrict__ ew, int E)
{
    int base = (blockIdx.x * blockDim.x + threadIdx.x) * 4;
    if (base + 4 <= E) {
        int4   s4 = *reinterpret_cast<const int4*>(src + base);
        int4   d4 = *reinterpret_cast<const int4*>(dst + base);
        float4 w4 = *reinterpret_cast<const float4*>(ew + base);
        float c0 = norm[s4.x] * w4.x;
        float c1 = norm[s4.y] * w4.y;
        float c2 = norm[s4.z] * w4.z;
        float c3 = norm[s4.w] * w4.w;
        int p0 = atomicAdd(&g_cursor[d4.x], 1);
        int p1 = atomicAdd(&g_cursor[d4.y], 1);
        int p2 = atomicAdd(&g_cursor[d4.z], 1);
        int p3 = atomicAdd(&g_cursor[d4.w], 1);
        g_perm[p0] = pack_edge(s4.x, c0);
        g_perm[p1] = pack_edge(s4.y, c1);
        g_perm[p2] = pack_edge(s4.z, c2);
        g_perm[p3] = pack_edge(s4.w, c3);
    } else {
        for (int k = base; k < E; k++) {
            int s = src[k];
            int d = dst[k];
            int pos = atomicAdd(&g_cursor[d], 1);
            g_perm[pos] = pack_edge(s, norm[s] * ew[k]);
        }
    }
}

// ===========================================================================
// Persistent gather with warp-level work stealing: each warp grabs chunks
// of 8 nodes from a global counter and processes 2 nodes at a time with
// half-warps (16 lanes x uint4 covering the 128-feature fp16 row).
// ===========================================================================
__device__ __forceinline__ void node_aggregate(int d, int lane16,
                                               const float* __restrict__ norm,
                                               const float* __restrict__ bias,
                                               float* __restrict__ out)
{
    int j   = g_row_ptr[d];
    int end = g_row_ptr[d + 1];

    float acc[8];
#pragma unroll
    for (int q = 0; q < 8; q++) acc[q] = 0.f;

    for (; j + 4 <= end; j += 4) {
        unsigned long long e[4];
#pragma unroll
        for (int q = 0; q < 4; q++) e[q] = g_perm[j + q];
#pragma unroll
        for (int q = 0; q < 4; q++) {
            int   s = (int)(unsigned)(e[q] & 0xffffffffull);
            float c = __uint_as_float((unsigned)(e[q] >> 32));
            uint4 r = *reinterpret_cast<const uint4*>(
                &g_hw[(size_t)s * OUT_FEATS + lane16 * 8]);
            float2 f0 = __half22float2(*reinterpret_cast<__half2*>(&r.x));
            float2 f1 = __half22float2(*reinterpret_cast<__half2*>(&r.y));
            float2 f2 = __half22float2(*reinterpret_cast<__half2*>(&r.z));
            float2 f3 = __half22float2(*reinterpret_cast<__half2*>(&r.w));
            acc[0] = fmaf(c, f0.x, acc[0]);
            acc[1] = fmaf(c, f0.y, acc[1]);
            acc[2] = fmaf(c, f1.x, acc[2]);
            acc[3] = fmaf(c, f1.y, acc[3]);
            acc[4] = fmaf(c, f2.x, acc[4]);
            acc[5] = fmaf(c, f2.y, acc[5]);
            acc[6] = fmaf(c, f3.x, acc[6]);
            acc[7] = fmaf(c, f3.y, acc[7]);
        }
    }
    for (; j < end; j++) {
        unsigned long long e = g_perm[j];
        int   s = (int)(unsigned)(e & 0xffffffffull);
        float c = __uint_as_float((unsigned)(e >> 32));
        uint4 r = *reinterpret_cast<const uint4*>(
            &g_hw[(size_t)s * OUT_FEATS + lane16 * 8]);
        float2 f0 = __half22float2(*reinterpret_cast<__half2*>(&r.x));
        float2 f1 = __half22float2(*reinterpret_cast<__half2*>(&r.y));
        float2 f2 = __half22float2(*reinterpret_cast<__half2*>(&r.z));
        float2 f3 = __half22float2(*reinterpret_cast<__half2*>(&r.w));
        acc[0] = fmaf(c, f0.x, acc[0]);
        acc[1] = fmaf(c, f0.y, acc[1]);
        acc[2] = fmaf(c, f1.x, acc[2]);
        acc[3] = fmaf(c, f1.y, acc[3]);
        acc[4] = fmaf(c, f2.x, acc[4]);
        acc[5] = fmaf(c, f2.y, acc[5]);
        acc[6] = fmaf(c, f3.x, acc[6]);
        acc[7] = fmaf(c, f3.y, acc[7]);
    }

    float  nd = norm[d];
    float4 b0 = reinterpret_cast<const float4*>(bias)[lane16 * 2];
    float4 b1 = reinterpret_cast<const float4*>(bias)[lane16 * 2 + 1];
    float4 r0, r1;
    r0.x = fmaxf(fmaf(acc[0], nd, b0.x), 0.f);
    r0.y = fmaxf(fmaf(acc[1], nd, b0.y), 0.f);
    r0.z = fmaxf(fmaf(acc[2], nd, b0.z), 0.f);
    r0.w = fmaxf(fmaf(acc[3], nd, b0.w), 0.f);
    r1.x = fmaxf(fmaf(acc[4], nd, b1.x), 0.f);
    r1.y = fmaxf(fmaf(acc[5], nd, b1.y), 0.f);
    r1.z = fmaxf(fmaf(acc[6], nd, b1.z), 0.f);
    r1.w = fmaxf(fmaf(acc[7], nd, b1.w), 0.f);
    reinterpret_cast<float4*>(out)[(size_t)d * 32 + lane16 * 2]     = r0;
    reinterpret_cast<float4*>(out)[(size_t)d * 32 + lane16 * 2 + 1] = r1;
}

#define GATHER_CHUNK 8

__global__ __launch_bounds__(256) void gather_kernel(
    const float* __restrict__ norm, const float* __restrict__ bias,
    float* __restrict__ out, int N)
{
    const int lane   = threadIdx.x & 31;
    const int lane16 = threadIdx.x & 15;
    const int half   = (threadIdx.x >> 4) & 1;

    for (;;) {
        int base = 0;
        if (lane == 0) base = atomicAdd(&g_node_ctr, GATHER_CHUNK);
        base = __shfl_sync(0xffffffffu, base, 0);
        if (base >= N) break;

#pragma unroll
        for (int it = 0; it < GATHER_CHUNK / 2; it++) {
            int d = base + it * 2 + half;
            if (d < N) node_aggregate(d, lane16, norm, bias, out);
        }
    }
}

// ===========================================================================
// Launch with fork-join (R13 structure; persistent gather grid).
// ===========================================================================
extern "C" void kernel_launch(void* const* d_in, const int* in_sizes, int n_in,
                              void* d_out, int out_size)
{
    const float* h    = (const float*)d_in[0];
    const float* W    = (const float*)d_in[1];
    const float* bias = (const float*)d_in[2];
    const float* norm = (const float*)d_in[3];
    const float* ew   = (const float*)d_in[4];
    const int*   src  = (const int*)d_in[5];
    const int*   dst  = (const int*)d_in[6];
    float* out = (float*)d_out;

    const int N  = in_sizes[3];
    const int E  = in_sizes[4];
    const int nb = (N + 255) / 256;

    static cudaStream_t s1 = nullptr;
    static cudaEvent_t  ev_fork = nullptr, ev_join = nullptr;
    if (s1 == nullptr) {
        cudaStreamCreateWithFlags(&s1, cudaStreamNonBlocking);
        cudaEventCreateWithFlags(&ev_fork, cudaEventDisableTiming);
        cudaEventCreateWithFlags(&ev_join, cudaEventDisableTiming);
    }

    // fork immediately: GEMM branch depends only on the capture root
    cudaEventRecord(ev_fork, 0);
    cudaStreamWaitEvent(s1, ev_fork, 0);

    // main stream: CSR build chain (counts pre-zeroed by previous run)
    hist_kernel<<<(E + 4 * 256 - 1) / (4 * 256), 256>>>(dst, E);          // k0
    scan_sums_kernel<<<nb, 256>>>(N);                                     // k1
    scan_write_kernel<<<nb, 256>>>(nb, N, E);                             // k2
    permute_kernel<<<(E + 4 * 256 - 1) / (4 * 256), 256>>>(src, dst, norm, ew, E); // k3 (profiled)

    // side stream: dense projection
    gemm_kernel<<<(N + GBM - 1) / GBM, 256, 0, s1>>>(h, W, N);            // k4
    cudaEventRecord(ev_join, s1);

    // join: gather needs both g_hw (s1) and the CSR arrays (stream 0)
    cudaStreamWaitEvent(0, ev_join, 0);
    gather_kernel<<<592, 256>>>(norm, bias, out, N);                      // k5 (persistent)
}

// round 16
// speedup vs baseline: 1.2356x; 1.2356x over previous
#include <cuda_runtime.h>
#include <cuda_fp16.h>

#define N_NODES   50000
#define IN_FEATS  256
#define OUT_FEATS 128
#define MAX_E     800000

// ---- scratch (device globals; no allocs allowed) ----
__device__ __half g_hw[(size_t)N_NODES * OUT_FEATS];  // projected features (fp16)
__device__ int    g_counts[N_NODES];                  // zeroed by scan_write each run
__device__ int    g_row_ptr[N_NODES + 1];
__device__ int    g_cursor[N_NODES];
__device__ int    g_bsum[256];
__device__ unsigned long long g_perm[MAX_E];          // packed (src, coeff)

// ===========================================================================
// PTX helpers
// ===========================================================================
__device__ __forceinline__ unsigned smem_addr_u32(const void* ptr)
{
    return static_cast<unsigned>(__cvta_generic_to_shared(ptr));
}

__device__ __forceinline__ void ldsm4(unsigned& x0, unsigned& x1,
                                      unsigned& x2, unsigned& x3, unsigned addr)
{
    asm volatile("ldmatrix.sync.aligned.m8n8.x4.shared.b16 {%0,%1,%2,%3}, [%4];"
                 : "=r"(x0), "=r"(x1), "=r"(x2), "=r"(x3)
                 : "r"(addr));
}

__device__ __forceinline__ void ldsm4t(unsigned& x0, unsigned& x1,
                                       unsigned& x2, unsigned& x3, unsigned addr)
{
    asm volatile("ldmatrix.sync.aligned.m8n8.x4.trans.shared.b16 {%0,%1,%2,%3}, [%4];"
                 : "=r"(x0), "=r"(x1), "=r"(x2), "=r"(x3)
                 : "r"(addr));
}

__device__ __forceinline__ void mma_16816(float& c0, float& c1, float& c2, float& c3,
                                          unsigned a0, unsigned a1, unsigned a2, unsigned a3,
                                          unsigned b0, unsigned b1)
{
    asm volatile(
        "mma.sync.aligned.m16n8k16.row.col.f32.f16.f16.f32 "
        "{%0,%1,%2,%3}, {%4,%5,%6,%7}, {%8,%9}, {%0,%1,%2,%3};"
        : "+f"(c0), "+f"(c1), "+f"(c2), "+f"(c3)
        : "r"(a0), "r"(a1), "r"(a2), "r"(a3), "r"(b0), "r"(b1));
}

// ===========================================================================
// Tensor-core GEMM (measured-best 27us version, verbatim):
// 128x128 block tile, BK=32, double-buffered, register-staged loads.
// ===========================================================================
#define GBM 128
#define A_PAD 40    // halves per Ash row (80 B)
#define B_PAD 136   // halves per Bsh row (272 B)

__global__ __launch_bounds__(256) void gemm_kernel(
    const float* __restrict__ hmat, const float* __restrict__ wmat, int M)
{
    __shared__ __align__(16) __half Ash[2][128][A_PAD];
    __shared__ __align__(16) __half Bsh[2][32][B_PAD];

    const int tid    = threadIdx.x;
    const int lane   = tid & 31;
    const int wid    = tid >> 5;
    const int warp_m = wid & 3;
    const int warp_n = wid >> 2;
    const int block_m = blockIdx.x * GBM;

    const int arow0 = tid >> 2;
    const int arow1 = (tid + 256) >> 2;
    const int acol0 = (tid & 3) * 8;
    const int brow0 = tid >> 4;
    const int brow1 = (tid + 256) >> 4;
    const int bcol0 = (tid & 15) * 8;

    float acc[2][8][4];
#pragma unroll
    for (int mt = 0; mt < 2; mt++)
#pragma unroll
        for (int nt = 0; nt < 8; nt++)
#pragma unroll
            for (int q = 0; q < 4; q++) acc[mt][nt][q] = 0.0f;

    const int ldrow = lane & 15;
    const int ldcol = (lane >> 4) * 8;

    float4 stA[2][2];
    float4 stB[2][2];

    // ---------------- prologue ----------------
    {
        const int grow0 = block_m + arow0;
        const int grow1 = block_m + arow1;
        stA[0][0] = stA[0][1] = make_float4(0.f, 0.f, 0.f, 0.f);
        stA[1][0] = stA[1][1] = make_float4(0.f, 0.f, 0.f, 0.f);
        if (grow0 < M) {
            const float* p = hmat + (size_t)grow0 * IN_FEATS + acol0;
            stA[0][0] = reinterpret_cast<const float4*>(p)[0];
            stA[0][1] = reinterpret_cast<const float4*>(p)[1];
        }
        if (grow1 < M) {
            const float* p = hmat + (size_t)grow1 * IN_FEATS + acol0;
            stA[1][0] = reinterpret_cast<const float4*>(p)[0];
            stA[1][1] = reinterpret_cast<const float4*>(p)[1];
        }
        {
            const float* p = wmat + (size_t)brow0 * OUT_FEATS + bcol0;
            stB[0][0] = reinterpret_cast<const float4*>(p)[0];
            stB[0][1] = reinterpret_cast<const float4*>(p)[1];
        }
        {
            const float* p = wmat + (size_t)brow1 * OUT_FEATS + bcol0;
            stB[1][0] = reinterpret_cast<const float4*>(p)[0];
            stB[1][1] = reinterpret_cast<const float4*>(p)[1];
        }
        __half2 pk[4];
        pk[0] = __floats2half2_rn(stA[0][0].x, stA[0][0].y);
        pk[1] = __floats2half2_rn(stA[0][0].z, stA[0][0].w);
        pk[2] = __floats2half2_rn(stA[0][1].x, stA[0][1].y);
        pk[3] = __floats2half2_rn(stA[0][1].z, stA[0][1].w);
        *reinterpret_cast<uint4*>(&Ash[0][arow0][acol0]) = *reinterpret_cast<const uint4*>(pk);
        pk[0] = __floats2half2_rn(stA[1][0].x, stA[1][0].y);
        pk[1] = __floats2half2_rn(stA[1][0].z, stA[1][0].w);
        pk[2] = __floats2half2_rn(stA[1][1].x, stA[1][1].y);
        pk[3] = __floats2half2_rn(stA[1][1].z, stA[1][1].w);
        *reinterpret_cast<uint4*>(&Ash[0][arow1][acol0]) = *reinterpret_cast<const uint4*>(pk);
        pk[0] = __floats2half2_rn(stB[0][0].x, stB[0][0].y);
        pk[1] = __floats2half2_rn(stB[0][0].z, stB[0][0].w);
        pk[2] = __floats2half2_rn(stB[0][1].x, stB[0][1].y);
        pk[3] = __floats2half2_rn(stB[0][1].z, stB[0][1].w);
        *reinterpret_cast<uint4*>(&Bsh[0][brow0][bcol0]) = *reinterpret_cast<const uint4*>(pk);
        pk[0] = __floats2half2_rn(stB[1][0].x, stB[1][0].y);
        pk[1] = __floats2half2_rn(stB[1][0].z, stB[1][0].w);
        pk[2] = __floats2half2_rn(stB[1][1].x, stB[1][1].y);
        pk[3] = __floats2half2_rn(stB[1][1].z, stB[1][1].w);
        *reinterpret_cast<uint4*>(&Bsh[0][brow1][bcol0]) = *reinterpret_cast<const uint4*>(pk);
    }
    __syncthreads();

    // ---------------- main loop ----------------
    int buf = 0;
    for (int k0 = 0; k0 < IN_FEATS; k0 += 32, buf ^= 1) {
        const bool has_next = (k0 + 32 < IN_FEATS);

        if (has_next) {
            const int kn = k0 + 32;
            const int grow0 = block_m + arow0;
            const int grow1 = block_m + arow1;
            stA[0][0] = stA[0][1] = make_float4(0.f, 0.f, 0.f, 0.f);
            stA[1][0] = stA[1][1] = make_float4(0.f, 0.f, 0.f, 0.f);
            if (grow0 < M) {
                const float* p = hmat + (size_t)grow0 * IN_FEATS + kn + acol0;
                stA[0][0] = reinterpret_cast<const float4*>(p)[0];
                stA[0][1] = reinterpret_cast<const float4*>(p)[1];
            }
            if (grow1 < M) {
                const float* p = hmat + (size_t)grow1 * IN_FEATS + kn + acol0;
                stA[1][0] = reinterpret_cast<const float4*>(p)[0];
                stA[1][1] = reinterpret_cast<const float4*>(p)[1];
            }
            {
                const float* p = wmat + (size_t)(kn + brow0) * OUT_FEATS + bcol0;
                stB[0][0] = reinterpret_cast<const float4*>(p)[0];
                stB[0][1] = reinterpret_cast<const float4*>(p)[1];
            }
            {
                const float* p = wmat + (size_t)(kn + brow1) * OUT_FEATS + bcol0;
                stB[1][0] = reinterpret_cast<const float4*>(p)[0];
                stB[1][1] = reinterpret_cast<const float4*>(p)[1];
            }
        }

#pragma unroll
        for (int kk = 0; kk < 32; kk += 16) {
            unsigned afrag[2][4];
#pragma unroll
            for (int mt = 0; mt < 2; mt++) {
                unsigned addr = smem_addr_u32(
                    &Ash[buf][warp_m * 32 + mt * 16 + ldrow][kk + ldcol]);
                ldsm4(afrag[mt][0], afrag[mt][1], afrag[mt][2], afrag[mt][3], addr);
            }
            unsigned bfrag[4][4];
#pragma unroll
            for (int pp = 0; pp < 4; pp++) {
                unsigned addr = smem_addr_u32(
                    &Bsh[buf][kk + ldrow][warp_n * 64 + pp * 16 + ldcol]);
                ldsm4t(bfrag[pp][0], bfrag[pp][1], bfrag[pp][2], bfrag[pp][3], addr);
            }
#pragma unroll
            for (int mt = 0; mt < 2; mt++) {
#pragma unroll
                for (int nt = 0; nt < 8; nt++) {
                    unsigned bu0 = bfrag[nt >> 1][(nt & 1) * 2];
                    unsigned bu1 = bfrag[nt >> 1][(nt & 1) * 2 + 1];
                    mma_16816(acc[mt][nt][0], acc[mt][nt][1],
                              acc[mt][nt][2], acc[mt][nt][3],
                              afrag[mt][0], afrag[mt][1],
                              afrag[mt][2], afrag[mt][3], bu0, bu1);
                }
            }
        }

        if (has_next) {
            const int nb_ = buf ^ 1;
            __half2 pk[4];
            pk[0] = __floats2half2_rn(stA[0][0].x, stA[0][0].y);
            pk[1] = __floats2half2_rn(stA[0][0].z, stA[0][0].w);
            pk[2] = __floats2half2_rn(stA[0][1].x, stA[0][1].y);
            pk[3] = __floats2half2_rn(stA[0][1].z, stA[0][1].w);
            *reinterpret_cast<uint4*>(&Ash[nb_][arow0][acol0]) = *reinterpret_cast<const uint4*>(pk);
            pk[0] = __floats2half2_rn(stA[1][0].x, stA[1][0].y);
            pk[1] = __floats2half2_rn(stA[1][0].z, stA[1][0].w);
            pk[2] = __floats2half2_rn(stA[1][1].x, stA[1][1].y);
            pk[3] = __floats2half2_rn(stA[1][1].z, stA[1][1].w);
            *reinterpret_cast<uint4*>(&Ash[nb_][arow1][acol0]) = *reinterpret_cast<const uint4*>(pk);
            pk[0] = __floats2half2_rn(stB[0][0].x, stB[0][0].y);
            pk[1] = __floats2half2_rn(stB[0][0].z, stB[0][0].w);
            pk[2] = __floats2half2_rn(stB[0][1].x, stB[0][1].y);
            pk[3] = __floats2half2_rn(stB[0][1].z, stB[0][1].w);
            *reinterpret_cast<uint4*>(&Bsh[nb_][brow0][bcol0]) = *reinterpret_cast<const uint4*>(pk);
            pk[0] = __floats2half2_rn(stB[1][0].x, stB[1][0].y);
            pk[1] = __floats2half2_rn(stB[1][0].z, stB[1][0].w);
            pk[2] = __floats2half2_rn(stB[1][1].x, stB[1][1].y);
            pk[3] = __floats2half2_rn(stB[1][1].z, stB[1][1].w);
            *reinterpret_cast<uint4*>(&Bsh[nb_][brow1][bcol0]) = *reinterpret_cast<const uint4*>(pk);
        }
        __syncthreads();
    }

    // ---- epilogue: fp16 store ----
    const int qrow = lane >> 2;
    const int qcol = lane & 3;
#pragma unroll
    for (int mt = 0; mt < 2; mt++) {
#pragma unroll
        for (int nt = 0; nt < 8; nt++) {
            int col  = warp_n * 64 + nt * 8 + qcol * 2;
            int row0 = block_m + warp_m * 32 + mt * 16 + qrow;
            int row1 = row0 + 8;
            if (row0 < M) {
                *reinterpret_cast<__half2*>(&g_hw[(size_t)row0 * OUT_FEATS + col]) =
                    __floats2half2_rn(acc[mt][nt][0], acc[mt][nt][1]);
            }
            if (row1 < M) {
                *reinterpret_cast<__half2*>(&g_hw[(size_t)row1 * OUT_FEATS + col]) =
                    __floats2half2_rn(acc[mt][nt][2], acc[mt][nt][3]);
            }
        }
    }
}

// ===========================================================================
// CSR build
// ===========================================================================
// Histogram, ILP-2: twice the blocks of ILP-4 -> more resident warps to hide
// RED latency (TLP instead of per-thread ILP).
__global__ void hist_kernel(const int* __restrict__ dst, int E)
{
    int base = (blockIdx.x * blockDim.x + threadIdx.x) * 2;
    if (base + 2 <= E) {
        int2 d2 = *reinterpret_cast<const int2*>(dst + base);
        atomicAdd(&g_counts[d2.x], 1);
        atomicAdd(&g_counts[d2.y], 1);
    } else if (base < E) {
        atomicAdd(&g_counts[dst[base]], 1);
    }
}

__global__ __launch_bounds__(256) void scan_sums_kernel(int N)
{
    __shared__ int sh[256];
    int i = blockIdx.x * 256 + threadIdx.x;
    sh[threadIdx.x] = (i < N) ? g_counts[i] : 0;
    __syncthreads();
#pragma unroll
    for (int s = 128; s > 0; s >>= 1) {
        if (threadIdx.x < s) sh[threadIdx.x] += sh[threadIdx.x + s];
        __syncthreads();
    }
    if (threadIdx.x == 0) g_bsum[blockIdx.x] = sh[0];
}

// Merged top-scan + local scan; initializes cursors and SELF-CLEANS counts.
__global__ __launch_bounds__(256) void scan_write_kernel(int nb, int N, int E)
{
    __shared__ int top[256];
    __shared__ int sh[256];
    const int t = threadIdx.x;

    int tv = (t < nb) ? g_bsum[t] : 0;
    top[t] = tv;
    __syncthreads();
#pragma unroll
    for (int s = 1; s < 256; s <<= 1) {
        int add = (t >= s) ? top[t - s] : 0;
        __syncthreads();
        top[t] += add;
        __syncthreads();
    }
    const int boff = (blockIdx.x > 0) ? top[blockIdx.x - 1] : 0;

    int i = blockIdx.x * 256 + t;
    int v = (i < N) ? g_counts[i] : 0;
    sh[t] = v;
    __syncthreads();
#pragma unroll
    for (int s = 1; s < 256; s <<= 1) {
        int add = (t >= s) ? sh[t - s] : 0;
        __syncthreads();
        sh[t] += add;
        __syncthreads();
    }
    if (i < N) {
        int rp = boff + sh[t] - v;
        g_row_ptr[i] = rp;
        g_cursor[i]  = rp;
        g_counts[i]  = 0;          // self-clean for next run
    }
    if (blockIdx.x == 0 && t == 0) g_row_ptr[N] = E;
}

__device__ __forceinline__ unsigned long long pack_edge(int s, float c)
{
    return (unsigned long long)(unsigned)s |
           ((unsigned long long)__float_as_uint(c) << 32);
}

// Permutation, ILP-2: twice the blocks of ILP-4 -> ~400K threads requested,
// chip capacity ~303K resident -> full occupancy; more concurrent ATOMs.
__global__ void permute_kernel(
    const int* __restrict__ src, const int* __restrict__ dst,
    const float* __restrict__ norm, const float* __restrict__ ew, int E)
{
    int base = (blockIdx.x * blockDim.x + threadIdx.x) * 2;
    if (base + 2 <= E) {
        int2   s2 = *reinterpret_cast<const int2*>(src + base);
        int2   d2 = *reinterpret_cast<const int2*>(dst + base);
        float2 w2 = *reinterpret_cast<const float2*>(ew + base);
        float c0 = norm[s2.x] * w2.x;
        float c1 = norm[s2.y] * w2.y;
        int p0 = atomicAdd(&g_cursor[d2.x], 1);
        int p1 = atomicAdd(&g_cursor[d2.y], 1);
        g_perm[p0] = pack_edge(s2.x, c0);
        g_perm[p1] = pack_edge(s2.y, c1);
    } else if (base < E) {
        int s = src[base];
        int d = dst[base];
        int pos = atomicAdd(&g_cursor[d], 1);
        g_perm[pos] = pack_edge(s, norm[s] * ew[base]);
    }
}

// ===========================================================================
// Gather-aggregate (R13 best-measured version, verbatim): HALF-warp per node,
// 16 lanes x uint4 (8 fp16 feats each), ILP-4 edge batches.
// ===========================================================================
__device__ __forceinline__ void edge_acc8(unsigned long long pe, int lane16,
                                          float* acc)
{
    int   s = (int)(unsigned)(pe & 0xffffffffull);
    float c = __uint_as_float((unsigned)(pe >> 32));
    uint4 r = *reinterpret_cast<const uint4*>(&g_hw[(size_t)s * OUT_FEATS + lane16 * 8]);
    float2 f0 = __half22float2(*reinterpret_cast<__half2*>(&r.x));
    float2 f1 = __half22float2(*reinterpret_cast<__half2*>(&r.y));
    float2 f2 = __half22float2(*reinterpret_cast<__half2*>(&r.z));
    float2 f3 = __half22float2(*reinterpret_cast<__half2*>(&r.w));
    acc[0] = fmaf(c, f0.x, acc[0]);
    acc[1] = fmaf(c, f0.y, acc[1]);
    acc[2] = fmaf(c, f1.x, acc[2]);
    acc[3] = fmaf(c, f1.y, acc[3]);
    acc[4] = fmaf(c, f2.x, acc[4]);
    acc[5] = fmaf(c, f2.y, acc[5]);
    acc[6] = fmaf(c, f3.x, acc[6]);
    acc[7] = fmaf(c, f3.y, acc[7]);
}

__global__ __launch_bounds__(256) void gather_kernel(
    const float* __restrict__ norm, const float* __restrict__ bias,
    float* __restrict__ out, int N)
{
    // 256 threads = 16 half-warps = 16 nodes per block
    int d = blockIdx.x * 16 + (threadIdx.x >> 4);
    if (d >= N) return;
    int lane16 = threadIdx.x & 15;

    int j   = g_row_ptr[d];
    int end = g_row_ptr[d + 1];

    float acc[8];
#pragma unroll
    for (int q = 0; q < 8; q++) acc[q] = 0.f;

    for (; j + 4 <= end; j += 4) {
        unsigned long long e0 = g_perm[j];
        unsigned long long e1 = g_perm[j + 1];
        unsigned long long e2 = g_perm[j + 2];
        unsigned long long e3 = g_perm[j + 3];
        edge_acc8(e0, lane16, acc);
        edge_acc8(e1, lane16, acc);
        edge_acc8(e2, lane16, acc);
        edge_acc8(e3, lane16, acc);
    }
    for (; j < end; j++) {
        edge_acc8(g_perm[j], lane16, acc);
    }

    float  nd = norm[d];
    float4 b0 = reinterpret_cast<const float4*>(bias)[lane16 * 2];
    float4 b1 = reinterpret_cast<const float4*>(bias)[lane16 * 2 + 1];
    float4 r0, r1;
    r0.x = fmaxf(fmaf(acc[0], nd, b0.x), 0.f);
    r0.y = fmaxf(fmaf(acc[1], nd, b0.y), 0.f);
    r0.z = fmaxf(fmaf(acc[2], nd, b0.z), 0.f);
    r0.w = fmaxf(fmaf(acc[3], nd, b0.w), 0.f);
    r1.x = fmaxf(fmaf(acc[4], nd, b1.x), 0.f);
    r1.y = fmaxf(fmaf(acc[5], nd, b1.y), 0.f);
    r1.z = fmaxf(fmaf(acc[6], nd, b1.z), 0.f);
    r1.w = fmaxf(fmaf(acc[7], nd, b1.w), 0.f);
    reinterpret_cast<float4*>(out)[(size_t)d * 32 + lane16 * 2]     = r0;
    reinterpret_cast<float4*>(out)[(size_t)d * 32 + lane16 * 2 + 1] = r1;
}

// ===========================================================================
// Launch with fork-join (R13 structure, unchanged).
// ===========================================================================
extern "C" void kernel_launch(void* const* d_in, const int* in_sizes, int n_in,
                              void* d_out, int out_size)
{
    const float* h    = (const float*)d_in[0];
    const float* W    = (const float*)d_in[1];
    const float* bias = (const float*)d_in[2];
    const float* norm = (const float*)d_in[3];
    const float* ew   = (const float*)d_in[4];
    const int*   src  = (const int*)d_in[5];
    const int*   dst  = (const int*)d_in[6];
    float* out = (float*)d_out;

    const int N  = in_sizes[3];
    const int E  = in_sizes[4];
    const int nb = (N + 255) / 256;

    static cudaStream_t s1 = nullptr;
    static cudaEvent_t  ev_fork = nullptr, ev_join = nullptr;
    if (s1 == nullptr) {
        cudaStreamCreateWithFlags(&s1, cudaStreamNonBlocking);
        cudaEventCreateWithFlags(&ev_fork, cudaEventDisableTiming);
        cudaEventCreateWithFlags(&ev_join, cudaEventDisableTiming);
    }

    // fork immediately: GEMM branch depends only on the capture root
    cudaEventRecord(ev_fork, 0);
    cudaStreamWaitEvent(s1, ev_fork, 0);

    // main stream: CSR build chain (counts pre-zeroed by previous run)
    hist_kernel<<<(E + 2 * 256 - 1) / (2 * 256), 256>>>(dst, E);          // k0
    scan_sums_kernel<<<nb, 256>>>(N);                                     // k1
    scan_write_kernel<<<nb, 256>>>(nb, N, E);                             // k2
    permute_kernel<<<(E + 2 * 256 - 1) / (2 * 256), 256>>>(src, dst, norm, ew, E); // k3 (profiled)

    // side stream: dense projection
    gemm_kernel<<<(N + GBM - 1) / GBM, 256, 0, s1>>>(h, W, N);            // k4
    cudaEventRecord(ev_join, s1);

    // join: gather needs both g_hw (s1) and the CSR arrays (stream 0)
    cudaStreamWaitEvent(0, ev_join, 0);
    gather_kernel<<<(N + 15) / 16, 256>>>(norm, bias, out, N);            // k5
}

// round 17
// speedup vs baseline: 1.2542x; 1.0151x over previous
#include <cuda_runtime.h>
#include <cuda_fp16.h>

#define N_NODES   50000
#define IN_FEATS  256
#define OUT_FEATS 128
#define MAX_E     800000

// ---- scratch (device globals; no allocs allowed) ----
__device__ __half g_hw[(size_t)N_NODES * OUT_FEATS];  // projected features (fp16)
__device__ int    g_counts[N_NODES];                  // zeroed by scan_write each run
__device__ int    g_row_ptr[N_NODES + 1];
__device__ int    g_cursor[N_NODES];
__device__ int    g_bsum[256];
__device__ unsigned long long g_perm[MAX_E];          // packed (src, coeff)

// ===========================================================================
// PTX helpers
// ===========================================================================
__device__ __forceinline__ unsigned smem_addr_u32(const void* ptr)
{
    return static_cast<unsigned>(__cvta_generic_to_shared(ptr));
}

__device__ __forceinline__ void ldsm4(unsigned& x0, unsigned& x1,
                                      unsigned& x2, unsigned& x3, unsigned addr)
{
    asm volatile("ldmatrix.sync.aligned.m8n8.x4.shared.b16 {%0,%1,%2,%3}, [%4];"
                 : "=r"(x0), "=r"(x1), "=r"(x2), "=r"(x3)
                 : "r"(addr));
}

__device__ __forceinline__ void ldsm4t(unsigned& x0, unsigned& x1,
                                       unsigned& x2, unsigned& x3, unsigned addr)
{
    asm volatile("ldmatrix.sync.aligned.m8n8.x4.trans.shared.b16 {%0,%1,%2,%3}, [%4];"
                 : "=r"(x0), "=r"(x1), "=r"(x2), "=r"(x3)
                 : "r"(addr));
}

__device__ __forceinline__ void mma_16816(float& c0, float& c1, float& c2, float& c3,
                                          unsigned a0, unsigned a1, unsigned a2, unsigned a3,
                                          unsigned b0, unsigned b1)
{
    asm volatile(
        "mma.sync.aligned.m16n8k16.row.col.f32.f16.f16.f32 "
        "{%0,%1,%2,%3}, {%4,%5,%6,%7}, {%8,%9}, {%0,%1,%2,%3};"
        : "+f"(c0), "+f"(c1), "+f"(c2), "+f"(c3)
        : "r"(a0), "r"(a1), "r"(a2), "r"(a3), "r"(b0), "r"(b1));
}

// ===========================================================================
// Tensor-core GEMM (measured-best 27us version, verbatim):
// 128x128 block tile, BK=32, double-buffered, register-staged loads.
// ===========================================================================
#define GBM 128
#define A_PAD 40    // halves per Ash row (80 B)
#define B_PAD 136   // halves per Bsh row (272 B)

__global__ __launch_bounds__(256) void gemm_kernel(
    const float* __restrict__ hmat, const float* __restrict__ wmat, int M)
{
    __shared__ __align__(16) __half Ash[2][128][A_PAD];
    __shared__ __align__(16) __half Bsh[2][32][B_PAD];

    const int tid    = threadIdx.x;
    const int lane   = tid & 31;
    const int wid    = tid >> 5;
    const int warp_m = wid & 3;
    const int warp_n = wid >> 2;
    const int block_m = blockIdx.x * GBM;

    const int arow0 = tid >> 2;
    const int arow1 = (tid + 256) >> 2;
    const int acol0 = (tid & 3) * 8;
    const int brow0 = tid >> 4;
    const int brow1 = (tid + 256) >> 4;
    const int bcol0 = (tid & 15) * 8;

    float acc[2][8][4];
#pragma unroll
    for (int mt = 0; mt < 2; mt++)
#pragma unroll
        for (int nt = 0; nt < 8; nt++)
#pragma unroll
            for (int q = 0; q < 4; q++) acc[mt][nt][q] = 0.0f;

    const int ldrow = lane & 15;
    const int ldcol = (lane >> 4) * 8;

    float4 stA[2][2];
    float4 stB[2][2];

    // ---------------- prologue ----------------
    {
        const int grow0 = block_m + arow0;
        const int grow1 = block_m + arow1;
        stA[0][0] = stA[0][1] = make_float4(0.f, 0.f, 0.f, 0.f);
        stA[1][0] = stA[1][1] = make_float4(0.f, 0.f, 0.f, 0.f);
        if (grow0 < M) {
            const float* p = hmat + (size_t)grow0 * IN_FEATS + acol0;
            stA[0][0] = reinterpret_cast<const float4*>(p)[0];
            stA[0][1] = reinterpret_cast<const float4*>(p)[1];
        }
        if (grow1 < M) {
            const float* p = hmat + (size_t)grow1 * IN_FEATS + acol0;
            stA[1][0] = reinterpret_cast<const float4*>(p)[0];
            stA[1][1] = reinterpret_cast<const float4*>(p)[1];
        }
        {
            const float* p = wmat + (size_t)brow0 * OUT_FEATS + bcol0;
            stB[0][0] = reinterpret_cast<const float4*>(p)[0];
            stB[0][1] = reinterpret_cast<const float4*>(p)[1];
        }
        {
            const float* p = wmat + (size_t)brow1 * OUT_FEATS + bcol0;
            stB[1][0] = reinterpret_cast<const float4*>(p)[0];
            stB[1][1] = reinterpret_cast<const float4*>(p)[1];
        }
        __half2 pk[4];
        pk[0] = __floats2half2_rn(stA[0][0].x, stA[0][0].y);
        pk[1] = __floats2half2_rn(stA[0][0].z, stA[0][0].w);
        pk[2] = __floats2half2_rn(stA[0][1].x, stA[0][1].y);
        pk[3] = __floats2half2_rn(stA[0][1].z, stA[0][1].w);
        *reinterpret_cast<uint4*>(&Ash[0][arow0][acol0]) = *reinterpret_cast<const uint4*>(pk);
        pk[0] = __floats2half2_rn(stA[1][0].x, stA[1][0].y);
        pk[1] = __floats2half2_rn(stA[1][0].z, stA[1][0].w);
        pk[2] = __floats2half2_rn(stA[1][1].x, stA[1][1].y);
        pk[3] = __floats2half2_rn(stA[1][1].z, stA[1][1].w);
        *reinterpret_cast<uint4*>(&Ash[0][arow1][acol0]) = *reinterpret_cast<const uint4*>(pk);
        pk[0] = __floats2half2_rn(stB[0][0].x, stB[0][0].y);
        pk[1] = __floats2half2_rn(stB[0][0].z, stB[0][0].w);
        pk[2] = __floats2half2_rn(stB[0][1].x, stB[0][1].y);
        pk[3] = __floats2half2_rn(stB[0][1].z, stB[0][1].w);
        *reinterpret_cast<uint4*>(&Bsh[0][brow0][bcol0]) = *reinterpret_cast<const uint4*>(pk);
        pk[0] = __floats2half2_rn(stB[1][0].x, stB[1][0].y);
        pk[1] = __floats2half2_rn(stB[1][0].z, stB[1][0].w);
        pk[2] = __floats2half2_rn(stB[1][1].x, stB[1][1].y);
        pk[3] = __floats2half2_rn(stB[1][1].z, stB[1][1].w);
        *reinterpret_cast<uint4*>(&Bsh[0][brow1][bcol0]) = *reinterpret_cast<const uint4*>(pk);
    }
    __syncthreads();

    // ---------------- main loop ----------------
    int buf = 0;
    for (int k0 = 0; k0 < IN_FEATS; k0 += 32, buf ^= 1) {
        const bool has_next = (k0 + 32 < IN_FEATS);

        if (has_next) {
            const int kn = k0 + 32;
            const int grow0 = block_m + arow0;
            const int grow1 = block_m + arow1;
            stA[0][0] = stA[0][1] = make_float4(0.f, 0.f, 0.f, 0.f);
            stA[1][0] = stA[1][1] = make_float4(0.f, 0.f, 0.f, 0.f);
            if (grow0 < M) {
                const float* p = hmat + (size_t)grow0 * IN_FEATS + kn + acol0;
                stA[0][0] = reinterpret_cast<const float4*>(p)[0];
                stA[0][1] = reinterpret_cast<const float4*>(p)[1];
            }
            if (grow1 < M) {
                const float* p = hmat + (size_t)grow1 * IN_FEATS + kn + acol0;
                stA[1][0] = reinterpret_cast<const float4*>(p)[0];
                stA[1][1] = reinterpret_cast<const float4*>(p)[1];
            }
            {
                const float* p = wmat + (size_t)(kn + brow0) * OUT_FEATS + bcol0;
                stB[0][0] = reinterpret_cast<const float4*>(p)[0];
                stB[0][1] = reinterpret_cast<const float4*>(p)[1];
            }
            {
                const float* p = wmat + (size_t)(kn + brow1) * OUT_FEATS + bcol0;
                stB[1][0] = reinterpret_cast<const float4*>(p)[0];
                stB[1][1] = reinterpret_cast<const float4*>(p)[1];
            }
        }

#pragma unroll
        for (int kk = 0; kk < 32; kk += 16) {
            unsigned afrag[2][4];
#pragma unroll
            for (int mt = 0; mt < 2; mt++) {
                unsigned addr = smem_addr_u32(
                    &Ash[buf][warp_m * 32 + mt * 16 + ldrow][kk + ldcol]);
                ldsm4(afrag[mt][0], afrag[mt][1], afrag[mt][2], afrag[mt][3], addr);
            }
            unsigned bfrag[4][4];
#pragma unroll
            for (int pp = 0; pp < 4; pp++) {
                unsigned addr = smem_addr_u32(
                    &Bsh[buf][kk + ldrow][warp_n * 64 + pp * 16 + ldcol]);
                ldsm4t(bfrag[pp][0], bfrag[pp][1], bfrag[pp][2], bfrag[pp][3], addr);
            }
#pragma unroll
            for (int mt = 0; mt < 2; mt++) {
#pragma unroll
                for (int nt = 0; nt < 8; nt++) {
                    unsigned bu0 = bfrag[nt >> 1][(nt & 1) * 2];
                    unsigned bu1 = bfrag[nt >> 1][(nt & 1) * 2 + 1];
                    mma_16816(acc[mt][nt][0], acc[mt][nt][1],
                              acc[mt][nt][2], acc[mt][nt][3],
                              afrag[mt][0], afrag[mt][1],
                              afrag[mt][2], afrag[mt][3], bu0, bu1);
                }
            }
        }

        if (has_next) {
            const int nb_ = buf ^ 1;
            __half2 pk[4];
            pk[0] = __floats2half2_rn(stA[0][0].x, stA[0][0].y);
            pk[1] = __floats2half2_rn(stA[0][0].z, stA[0][0].w);
            pk[2] = __floats2half2_rn(stA[0][1].x, stA[0][1].y);
            pk[3] = __floats2half2_rn(stA[0][1].z, stA[0][1].w);
            *reinterpret_cast<uint4*>(&Ash[nb_][arow0][acol0]) = *reinterpret_cast<const uint4*>(pk);
            pk[0] = __floats2half2_rn(stA[1][0].x, stA[1][0].y);
            pk[1] = __floats2half2_rn(stA[1][0].z, stA[1][0].w);
            pk[2] = __floats2half2_rn(stA[1][1].x, stA[1][1].y);
            pk[3] = __floats2half2_rn(stA[1][1].z, stA[1][1].w);
            *reinterpret_cast<uint4*>(&Ash[nb_][arow1][acol0]) = *reinterpret_cast<const uint4*>(pk);
            pk[0] = __floats2half2_rn(stB[0][0].x, stB[0][0].y);
            pk[1] = __floats2half2_rn(stB[0][0].z, stB[0][0].w);
            pk[2] = __floats2half2_rn(stB[0][1].x, stB[0][1].y);
            pk[3] = __floats2half2_rn(stB[0][1].z, stB[0][1].w);
            *reinterpret_cast<uint4*>(&Bsh[nb_][brow0][bcol0]) = *reinterpret_cast<const uint4*>(pk);
            pk[0] = __floats2half2_rn(stB[1][0].x, stB[1][0].y);
            pk[1] = __floats2half2_rn(stB[1][0].z, stB[1][0].w);
            pk[2] = __floats2half2_rn(stB[1][1].x, stB[1][1].y);
            pk[3] = __floats2half2_rn(stB[1][1].z, stB[1][1].w);
            *reinterpret_cast<uint4*>(&Bsh[nb_][brow1][bcol0]) = *reinterpret_cast<const uint4*>(pk);
        }
        __syncthreads();
    }

    // ---- epilogue: fp16 store ----
    const int qrow = lane >> 2;
    const int qcol = lane & 3;
#pragma unroll
    for (int mt = 0; mt < 2; mt++) {
#pragma unroll
        for (int nt = 0; nt < 8; nt++) {
            int col  = warp_n * 64 + nt * 8 + qcol * 2;
            int row0 = block_m + warp_m * 32 + mt * 16 + qrow;
            int row1 = row0 + 8;
            if (row0 < M) {
                *reinterpret_cast<__half2*>(&g_hw[(size_t)row0 * OUT_FEATS + col]) =
                    __floats2half2_rn(acc[mt][nt][0], acc[mt][nt][1]);
            }
            if (row1 < M) {
                *reinterpret_cast<__half2*>(&g_hw[(size_t)row1 * OUT_FEATS + col]) =
                    __floats2half2_rn(acc[mt][nt][2], acc[mt][nt][3]);
            }
        }
    }
}

// ===========================================================================
// CSR build
// ===========================================================================
// Histogram, ILP-1: maximum thread-level parallelism; RED fire-and-forget.
__global__ void hist_kernel(const int* __restrict__ dst, int E)
{
    int e = blockIdx.x * blockDim.x + threadIdx.x;
    if (e < E) atomicAdd(&g_counts[dst[e]], 1);
}

__global__ __launch_bounds__(256) void scan_sums_kernel(int N)
{
    __shared__ int sh[256];
    int i = blockIdx.x * 256 + threadIdx.x;
    sh[threadIdx.x] = (i < N) ? g_counts[i] : 0;
    __syncthreads();
#pragma unroll
    for (int s = 128; s > 0; s >>= 1) {
        if (threadIdx.x < s) sh[threadIdx.x] += sh[threadIdx.x + s];
        __syncthreads();
    }
    if (threadIdx.x == 0) g_bsum[blockIdx.x] = sh[0];
}

// Merged top-scan + local scan; initializes cursors and SELF-CLEANS counts.
__global__ __launch_bounds__(256) void scan_write_kernel(int nb, int N, int E)
{
    __shared__ int top[256];
    __shared__ int sh[256];
    const int t = threadIdx.x;

    int tv = (t < nb) ? g_bsum[t] : 0;
    top[t] = tv;
    __syncthreads();
#pragma unroll
    for (int s = 1; s < 256; s <<= 1) {
        int add = (t >= s) ? top[t - s] : 0;
        __syncthreads();
        top[t] += add;
        __syncthreads();
    }
    const int boff = (blockIdx.x > 0) ? top[blockIdx.x - 1] : 0;

    int i = blockIdx.x * 256 + t;
    int v = (i < N) ? g_counts[i] : 0;
    sh[t] = v;
    __syncthreads();
#pragma unroll
    for (int s = 1; s < 256; s <<= 1) {
        int add = (t >= s) ? sh[t - s] : 0;
        __syncthreads();
        sh[t] += add;
        __syncthreads();
    }
    if (i < N) {
        int rp = boff + sh[t] - v;
        g_row_ptr[i] = rp;
        g_cursor[i]  = rp;
        g_counts[i]  = 0;          // self-clean for next run
    }
    if (blockIdx.x == 0 && t == 0) g_row_ptr[N] = E;
}

__device__ __forceinline__ unsigned long long pack_edge(int s, float c)
{
    return (unsigned long long)(unsigned)s |
           ((unsigned long long)__float_as_uint(c) << 32);
}

// Permutation, ILP-1: one edge per thread, maximal resident-warp count so
// the largest possible number of ATOMGs is in flight chip-wide.
__global__ void permute_kernel(
    const int* __restrict__ src, const int* __restrict__ dst,
    const float* __restrict__ norm, const float* __restrict__ ew, int E)
{
    int e = blockIdx.x * blockDim.x + threadIdx.x;
    if (e >= E) return;
    int s = src[e];
    int d = dst[e];
    float c = norm[s] * ew[e];
    int pos = atomicAdd(&g_cursor[d], 1);
    g_perm[pos] = pack_edge(s, c);
}

// ===========================================================================
// Gather-aggregate (R13/R16 best-measured version, verbatim): HALF-warp per
// node, 16 lanes x uint4 (8 fp16 feats each), ILP-4 edge batches.
// ===========================================================================
__device__ __forceinline__ void edge_acc8(unsigned long long pe, int lane16,
                                          float* acc)
{
    int   s = (int)(unsigned)(pe & 0xffffffffull);
    float c = __uint_as_float((unsigned)(pe >> 32));
    uint4 r = *reinterpret_cast<const uint4*>(&g_hw[(size_t)s * OUT_FEATS + lane16 * 8]);
    float2 f0 = __half22float2(*reinterpret_cast<__half2*>(&r.x));
    float2 f1 = __half22float2(*reinterpret_cast<__half2*>(&r.y));
    float2 f2 = __half22float2(*reinterpret_cast<__half2*>(&r.z));
    float2 f3 = __half22float2(*reinterpret_cast<__half2*>(&r.w));
    acc[0] = fmaf(c, f0.x, acc[0]);
    acc[1] = fmaf(c, f0.y, acc[1]);
    acc[2] = fmaf(c, f1.x, acc[2]);
    acc[3] = fmaf(c, f1.y, acc[3]);
    acc[4] = fmaf(c, f2.x, acc[4]);
    acc[5] = fmaf(c, f2.y, acc[5]);
    acc[6] = fmaf(c, f3.x, acc[6]);
    acc[7] = fmaf(c, f3.y, acc[7]);
}

__global__ __launch_bounds__(256) void gather_kernel(
    const float* __restrict__ norm, const float* __restrict__ bias,
    float* __restrict__ out, int N)
{
    // 256 threads = 16 half-warps = 16 nodes per block
    int d = blockIdx.x * 16 + (threadIdx.x >> 4);
    if (d >= N) return;
    int lane16 = threadIdx.x & 15;

    int j   = g_row_ptr[d];
    int end = g_row_ptr[d + 1];

    float acc[8];
#pragma unroll
    for (int q = 0; q < 8; q++) acc[q] = 0.f;

    for (; j + 4 <= end; j += 4) {
        unsigned long long e0 = g_perm[j];
        unsigned long long e1 = g_perm[j + 1];
        unsigned long long e2 = g_perm[j + 2];
        unsigned long long e3 = g_perm[j + 3];
        edge_acc8(e0, lane16, acc);
        edge_acc8(e1, lane16, acc);
        edge_acc8(e2, lane16, acc);
        edge_acc8(e3, lane16, acc);
    }
    for (; j < end; j++) {
        edge_acc8(g_perm[j], lane16, acc);
    }

    float  nd = norm[d];
    float4 b0 = reinterpret_cast<const float4*>(bias)[lane16 * 2];
    float4 b1 = reinterpret_cast<const float4*>(bias)[lane16 * 2 + 1];
    float4 r0, r1;
    r0.x = fmaxf(fmaf(acc[0], nd, b0.x), 0.f);
    r0.y = fmaxf(fmaf(acc[1], nd, b0.y), 0.f);
    r0.z = fmaxf(fmaf(acc[2], nd, b0.z), 0.f);
    r0.w = fmaxf(fmaf(acc[3], nd, b0.w), 0.f);
    r1.x = fmaxf(fmaf(acc[4], nd, b1.x), 0.f);
    r1.y = fmaxf(fmaf(acc[5], nd, b1.y), 0.f);
    r1.z = fmaxf(fmaf(acc[6], nd, b1.z), 0.f);
    r1.w = fmaxf(fmaf(acc[7], nd, b1.w), 0.f);
    reinterpret_cast<float4*>(out)[(size_t)d * 32 + lane16 * 2]     = r0;
    reinterpret_cast<float4*>(out)[(size_t)d * 32 + lane16 * 2 + 1] = r1;
}

// ===========================================================================
// Launch with fork-join (R16 structure, unchanged).
// ===========================================================================
extern "C" void kernel_launch(void* const* d_in, const int* in_sizes, int n_in,
                              void* d_out, int out_size)
{
    const float* h    = (const float*)d_in[0];
    const float* W    = (const float*)d_in[1];
    const float* bias = (const float*)d_in[2];
    const float* norm = (const float*)d_in[3];
    const float* ew   = (const float*)d_in[4];
    const int*   src  = (const int*)d_in[5];
    const int*   dst  = (const int*)d_in[6];
    float* out = (float*)d_out;

    const int N  = in_sizes[3];
    const int E  = in_sizes[4];
    const int nb = (N + 255) / 256;

    static cudaStream_t s1 = nullptr;
    static cudaEvent_t  ev_fork = nullptr, ev_join = nullptr;
    if (s1 == nullptr) {
        cudaStreamCreateWithFlags(&s1, cudaStreamNonBlocking);
        cudaEventCreateWithFlags(&ev_fork, cudaEventDisableTiming);
        cudaEventCreateWithFlags(&ev_join, cudaEventDisableTiming);
    }

    // fork immediately: GEMM branch depends only on the capture root
    cudaEventRecord(ev_fork, 0);
    cudaStreamWaitEvent(s1, ev_fork, 0);

    // main stream: CSR build chain (counts pre-zeroed by previous run)
    hist_kernel<<<(E + 255) / 256, 256>>>(dst, E);                        // k0
    scan_sums_kernel<<<nb, 256>>>(N);                                     // k1
    scan_write_kernel<<<nb, 256>>>(nb, N, E);                             // k2
    permute_kernel<<<(E + 255) / 256, 256>>>(src, dst, norm, ew, E);      // k3 (profiled)

    // side stream: dense projection
    gemm_kernel<<<(N + GBM - 1) / GBM, 256, 0, s1>>>(h, W, N);            // k4
    cudaEventRecord(ev_join, s1);

    // join: gather needs both g_hw (s1) and the CSR arrays (stream 0)
    cudaStreamWaitEvent(0, ev_join, 0);
    gather_kernel<<<(N + 15) / 16, 256>>>(norm, bias, out, N);            // k5
}